// round 1
// baseline (speedup 1.0000x reference)
#include <cuda_runtime.h>

// Problem dims
#define BN_ 32
#define CN_ 512
#define C2_ 256
#define MN_ 1024

// Scratch (device globals: allocation-free rule)
__device__ float g_wkv[CN_ * CN_];                    // stacked [Wk; Wv] 512x512
__device__ float g_bkv[CN_];                          // stacked bias
__device__ float g_kv[BN_ * CN_ * MN_];               // per-batch [512 x 1024]: rows 0-255 = k, 256-511 = v
__device__ float g_s[BN_ * MN_];                      // channel sums of k
__device__ float g_attn[(size_t)BN_ * MN_ * MN_];     // [B,1024,1024]
__device__ float g_omid[BN_ * MN_ * C2_];             // attn @ V result [B,1024,256]

// ---------- packed f32x2 helpers (Blackwell FFMA2) ----------
__device__ __forceinline__ unsigned long long f2fma(unsigned long long a,
                                                    unsigned long long b,
                                                    unsigned long long c) {
    unsigned long long d;
    asm("fma.rn.f32x2 %0, %1, %2, %3;" : "=l"(d) : "l"(a), "l"(b), "l"(c));
    return d;
}
__device__ __forceinline__ unsigned long long fdup(float x) {
    unsigned long long r;
    asm("mov.b64 %0, {%1, %1};" : "=l"(r) : "f"(x));
    return r;
}
__device__ __forceinline__ unsigned long long fpack(float lo, float hi) {
    unsigned long long r;
    asm("mov.b64 %0, {%1, %2};" : "=l"(r) : "f"(lo), "f"(hi));
    return r;
}
__device__ __forceinline__ float2 funpack(unsigned long long v) {
    float2 r;
    asm("mov.b64 {%0, %1}, %2;" : "=f"(r.x), "=f"(r.y) : "l"(v));
    return r;
}

// ---------- small kernels ----------
__global__ void pack_wkv_kernel(const float* __restrict__ Wk, const float* __restrict__ bk,
                                const float* __restrict__ Wv, const float* __restrict__ bv) {
    int i = blockIdx.x * 256 + threadIdx.x;
    if (i < CN_ * CN_)
        g_wkv[i] = (i < C2_ * CN_) ? Wk[i] : Wv[i - C2_ * CN_];
    if (i < CN_)
        g_bkv[i] = (i < C2_) ? bk[i] : bv[i - C2_];
}

__global__ void colsum_kernel() {
    int idx = blockIdx.x * blockDim.x + threadIdx.x;   // 32768 total
    int b = idx >> 10, m = idx & 1023;
    const float* p = g_kv + (size_t)b * (CN_ * MN_) + m;
    float acc = 0.f;
#pragma unroll 8
    for (int c = 0; c < C2_; c++) acc += p[(size_t)c * MN_];
    g_s[idx] = acc;
}

__global__ __launch_bounds__(256) void softmax_kernel() {
    size_t row = blockIdx.x;
    float* p = g_attn + row * MN_;
    int t = threadIdx.x;
    float4 v = *(float4*)&p[t * 4];

    __shared__ float red[8];
    __shared__ float bval[2];

    float mx = fmaxf(fmaxf(v.x, v.y), fmaxf(v.z, v.w));
#pragma unroll
    for (int o = 16; o > 0; o >>= 1) mx = fmaxf(mx, __shfl_xor_sync(0xffffffffu, mx, o));
    if ((t & 31) == 0) red[t >> 5] = mx;
    __syncthreads();
    if (t == 0) {
        float m = red[0];
#pragma unroll
        for (int i = 1; i < 8; i++) m = fmaxf(m, red[i]);
        bval[0] = m;
    }
    __syncthreads();
    mx = bval[0];

    v.x = __expf(v.x - mx);
    v.y = __expf(v.y - mx);
    v.z = __expf(v.z - mx);
    v.w = __expf(v.w - mx);
    float sm = v.x + v.y + v.z + v.w;
#pragma unroll
    for (int o = 16; o > 0; o >>= 1) sm += __shfl_xor_sync(0xffffffffu, sm, o);
    __syncthreads();                 // red[] reuse
    if ((t & 31) == 0) red[t >> 5] = sm;
    __syncthreads();
    if (t == 0) {
        float s = 0.f;
#pragma unroll
        for (int i = 0; i < 8; i++) s += red[i];
        bval[1] = 1.f / s;
    }
    __syncthreads();
    float inv = bval[1];
    v.x *= inv; v.y *= inv; v.z *= inv; v.w *= inv;
    *(float4*)&p[t * 4] = v;
}

// ---------- generic batched tiled SGEMM: 128x128 tile, BK=8, 8x8 microtile ----------
// AKM=false: A is row-major [m][k] (lda = k-stride of a row)
// AKM=true : A is K-major  [k][m] (lda = m-stride of a k-row)   [used for k^T k]
// EPI: 0 = none, 1 = +bias(aux1[r]), 2 = cov transform (aux1 = s, per batch),
//      3 = +aux1[r] + residual aux2[r*ldc + c]
template <bool AKM, int EPI>
__global__ __launch_bounds__(256, 2)
void sgemm128(const float* __restrict__ A, int lda, size_t sA,
              const float* __restrict__ B, int ldb, size_t sB,
              float* __restrict__ Cp, int ldc, size_t sC,
              int Kg,
              const float* __restrict__ aux1, size_t sX1,
              const float* __restrict__ aux2, size_t sX2) {
    __shared__ float As[8][128];
    __shared__ float Bs[8][128];

    int bz = blockIdx.z;
    A += (size_t)bz * sA;
    B += (size_t)bz * sB;
    Cp += (size_t)bz * sC;
    const float* s1 = aux1 + (size_t)bz * sX1;
    const float* s2 = aux2 + (size_t)bz * sX2;

    int m0 = blockIdx.y * 128, n0 = blockIdx.x * 128;
    int t = threadIdx.x;
    int tx = t & 15, ty = t >> 4;

    unsigned long long acc[8][4];
#pragma unroll
    for (int i = 0; i < 8; i++)
#pragma unroll
        for (int j = 0; j < 4; j++) acc[i][j] = 0ULL;

    for (int k0 = 0; k0 < Kg; k0 += 8) {
        __syncthreads();
        if (AKM) {
            int kr = t >> 5, mc = (t & 31) * 4;
            *(float4*)&As[kr][mc] = *(const float4*)&A[(size_t)(k0 + kr) * lda + m0 + mc];
        } else {
            int ar = t >> 1, ac = (t & 1) * 4;
            float4 va = *(const float4*)&A[(size_t)(m0 + ar) * lda + k0 + ac];
            As[ac + 0][ar] = va.x;
            As[ac + 1][ar] = va.y;
            As[ac + 2][ar] = va.z;
            As[ac + 3][ar] = va.w;
        }
        {
            int kr = t >> 5, nc = (t & 31) * 4;
            *(float4*)&Bs[kr][nc] = *(const float4*)&B[(size_t)(k0 + kr) * ldb + n0 + nc];
        }
        __syncthreads();

#pragma unroll
        for (int kk = 0; kk < 8; kk++) {
            float4 a0 = *(float4*)&As[kk][ty * 8];
            float4 a1 = *(float4*)&As[kk][ty * 8 + 4];
            float4 b0 = *(float4*)&Bs[kk][tx * 8];
            float4 b1 = *(float4*)&Bs[kk][tx * 8 + 4];
            unsigned long long bb[4];
            bb[0] = fpack(b0.x, b0.y);
            bb[1] = fpack(b0.z, b0.w);
            bb[2] = fpack(b1.x, b1.y);
            bb[3] = fpack(b1.z, b1.w);
            float av[8] = {a0.x, a0.y, a0.z, a0.w, a1.x, a1.y, a1.z, a1.w};
#pragma unroll
            for (int i = 0; i < 8; i++) {
                unsigned long long ad = fdup(av[i]);
#pragma unroll
                for (int j = 0; j < 4; j++) acc[i][j] = f2fma(ad, bb[j], acc[i][j]);
            }
        }
    }

    // epilogue
    const float INV_M = 1.0f / 1024.0f;
    const float INV_M2 = INV_M * INV_M;
    float sc[8];
    if (EPI == 2) {
        float4 c0 = *(const float4*)&s1[n0 + tx * 8];
        float4 c1 = *(const float4*)&s1[n0 + tx * 8 + 4];
        sc[0] = c0.x; sc[1] = c0.y; sc[2] = c0.z; sc[3] = c0.w;
        sc[4] = c1.x; sc[5] = c1.y; sc[6] = c1.z; sc[7] = c1.w;
    }
#pragma unroll
    for (int i = 0; i < 8; i++) {
        int r = m0 + ty * 8 + i;
        float o[8];
#pragma unroll
        for (int j = 0; j < 4; j++) {
            float2 p = funpack(acc[i][j]);
            o[2 * j] = p.x;
            o[2 * j + 1] = p.y;
        }
        if (EPI == 1) {
            float bb_ = s1[r];
#pragma unroll
            for (int j = 0; j < 8; j++) o[j] += bb_;
        } else if (EPI == 2) {
            float sr = s1[r];
#pragma unroll
            for (int j = 0; j < 8; j++)
                o[j] = (o[j] * INV_M - sr * sc[j] * INV_M2) * 0.0625f;
        } else if (EPI == 3) {
            float bb_ = s1[r];
            float4 x0 = *(const float4*)&s2[(size_t)r * ldc + n0 + tx * 8];
            float4 x1 = *(const float4*)&s2[(size_t)r * ldc + n0 + tx * 8 + 4];
            o[0] += bb_ + x0.x; o[1] += bb_ + x0.y; o[2] += bb_ + x0.z; o[3] += bb_ + x0.w;
            o[4] += bb_ + x1.x; o[5] += bb_ + x1.y; o[6] += bb_ + x1.z; o[7] += bb_ + x1.w;
        }
        float4 w0 = {o[0], o[1], o[2], o[3]};
        float4 w1 = {o[4], o[5], o[6], o[7]};
        *(float4*)&Cp[(size_t)r * ldc + n0 + tx * 8] = w0;
        *(float4*)&Cp[(size_t)r * ldc + n0 + tx * 8 + 4] = w1;
    }
}

extern "C" void kernel_launch(void* const* d_in, const int* in_sizes, int n_in,
                              void* d_out, int out_size) {
    const float* x  = (const float*)d_in[0];
    const float* Wk = (const float*)d_in[1];
    const float* bk = (const float*)d_in[2];
    const float* Wv = (const float*)d_in[3];
    const float* bv = (const float*)d_in[4];
    const float* Wo = (const float*)d_in[5];
    const float* bo = (const float*)d_in[6];
    float* out = (float*)d_out;

    float *kv, *s, *attn, *omid, *wkv, *bkv;
    cudaGetSymbolAddress((void**)&kv,   g_kv);
    cudaGetSymbolAddress((void**)&s,    g_s);
    cudaGetSymbolAddress((void**)&attn, g_attn);
    cudaGetSymbolAddress((void**)&omid, g_omid);
    cudaGetSymbolAddress((void**)&wkv,  g_wkv);
    cudaGetSymbolAddress((void**)&bkv,  g_bkv);

    // 1. stack Wk/Wv and biases
    pack_wkv_kernel<<<1024, 256>>>(Wk, bk, Wv, bv);

    // 2. kv[b] = Wkv @ x[b] + bkv     [512 x 1024] per batch
    sgemm128<false, 1><<<dim3(8, 4, 32), 256>>>(
        wkv, 512, 0, x, 1024, 524288, kv, 1024, 524288, 512, bkv, 0, nullptr, 0);

    // 3. s[b][m] = sum_c k[b][c][m]
    colsum_kernel<<<128, 256>>>();

    // 4. attn_pre[b] = ((k^T k)/M - s s^T / M^2) * c2^-0.5   [1024 x 1024]
    sgemm128<true, 2><<<dim3(8, 8, 32), 256>>>(
        kv, 1024, 524288, kv, 1024, 524288, attn, 1024, 1048576, 256, s, 1024, nullptr, 0);

    // 5. row softmax in place
    softmax_kernel<<<32768, 256>>>();

    // 6. omid[b] = attn[b] @ V[b]   (V = v-buffer reinterpreted [1024 x 256])
    sgemm128<false, 0><<<dim3(2, 8, 32), 256>>>(
        attn, 1024, 1048576, kv + 262144, 256, 524288, omid, 256, 262144, 1024,
        nullptr, 0, nullptr, 0);

    // 7. out[b] = Wo @ omid[b]-reinterp[256 x 1024] + bo + x[b]
    sgemm128<false, 3><<<dim3(8, 4, 32), 256>>>(
        Wo, 256, 0, omid, 1024, 262144, out, 1024, 524288, 256, bo, 0, x, 524288);
}

// round 3
// speedup vs baseline: 3.6774x; 3.6774x over previous
#include <cuda_runtime.h>
#include <cuda_bf16.h>
#include <cstdint>

#define BN 32
#define CIN 512
#define C2 256
#define MM 1024

// ---------------- scratch (device globals; allocation-free rule) ----------------
__device__ __align__(1024) __nv_bfloat16 g_xT[(size_t)BN * MM * CIN];     // [b][m][in]
__device__ __align__(1024) __nv_bfloat16 g_wkv[CIN * CIN];                // [out c][in]
__device__ float g_bkv[CIN];
__device__ __align__(1024) __nv_bfloat16 g_wo[CIN * C2];                  // [out][c]
__device__ __align__(1024) __nv_bfloat16 g_kv[(size_t)BN * CIN * MM];     // [b][c][m] rows 0-255 k, 256-511 v
__device__ __align__(1024) __nv_bfloat16 g_kT[(size_t)BN * MM * C2];      // [b][m][c]
__device__ __align__(1024) __nv_bfloat16 g_vT[(size_t)BN * C2 * MM];      // [b][c][n]  (= V^T)
__device__ float g_s[BN * MM];
__device__ __align__(1024) __nv_bfloat16 g_attn[(size_t)BN * MM * MM];    // logits -> attn (in place)
__device__ __align__(1024) __nv_bfloat16 g_omid[(size_t)BN * MM * C2];    // [b][m][c] linear
__device__ __align__(1024) __nv_bfloat16 g_projB[(size_t)BN * MM * C2];   // [b][m][c'] for proj GEMM

// ---------------- helpers ----------------
__device__ __forceinline__ uint32_t smem_u32(const void* p) {
    uint32_t a;
    asm("{ .reg .u64 t; cvta.to.shared.u64 t, %1; cvt.u32.u64 %0, t; }" : "=r"(a) : "l"(p));
    return a;
}
__device__ __forceinline__ uint32_t bf16pack(float lo, float hi) {
    uint32_t r;
    asm("cvt.rn.bf16x2.f32 %0, %1, %2;" : "=r"(r) : "f"(hi), "f"(lo));
    return r;
}
#define CP16(dst, src) \
    asm volatile("cp.async.cg.shared.global [%0], [%1], 16;" :: "r"(dst), "l"(src) : "memory")
#define CPCOMMIT() asm volatile("cp.async.commit_group;" ::: "memory")
#define CPWAIT(n) asm volatile("cp.async.wait_group %0;" :: "n"(n) : "memory")

__device__ __forceinline__ void ldsm_x4(uint32_t* r, uint32_t addr) {
    asm volatile("ldmatrix.sync.aligned.m8n8.x4.shared.b16 {%0,%1,%2,%3}, [%4];"
        : "=r"(r[0]), "=r"(r[1]), "=r"(r[2]), "=r"(r[3]) : "r"(addr));
}
__device__ __forceinline__ void ldsm_x2(uint32_t* r, uint32_t addr) {
    asm volatile("ldmatrix.sync.aligned.m8n8.x2.shared.b16 {%0,%1}, [%2];"
        : "=r"(r[0]), "=r"(r[1]) : "r"(addr));
}
__device__ __forceinline__ void mma16816(float* c, const uint32_t* a, const uint32_t* b) {
    asm volatile("mma.sync.aligned.m16n8k16.row.col.f32.bf16.bf16.f32 "
        "{%0,%1,%2,%3}, {%4,%5,%6,%7}, {%8,%9}, {%0,%1,%2,%3};"
        : "+f"(c[0]), "+f"(c[1]), "+f"(c[2]), "+f"(c[3])
        : "r"(a[0]), "r"(a[1]), "r"(a[2]), "r"(a[3]), "r"(b[0]), "r"(b[1]));
}

// ---------------- HMMA GEMM: 128x128 CTA tile, BK=32, 8 warps of 64x32 ----------------
// D[i][j] = sum_k A[m0+i][k] * B[n0+j][k]; A,B K-major bf16 in gmem.
// Smem tiles 128 rows x 40 bf16 (80B row stride -> conflict-free ldmatrix).
// EPI: 0 none (bf16 out), 1 +aux1[row] (bf16), 2 cov transform (aux1=s; bf16),
//      3 +aux1[row] + aux2 residual (fp32 out)
template <int EPI>
__global__ __launch_bounds__(256, 2)
void mma_gemm(const __nv_bfloat16* __restrict__ A, int lda, size_t sA,
              const __nv_bfloat16* __restrict__ B, int ldb, size_t sB,
              void* __restrict__ Cv, int ldc, size_t sC, int K,
              const float* __restrict__ aux1, size_t sX1,
              const float* __restrict__ aux2, size_t sX2) {
    __shared__ __align__(128) char smem[40960];   // [buf][A|B] tiles of 10240B
    uint32_t sbase = smem_u32(smem);
    int t = threadIdx.x, l = t & 31, w = t >> 5;
    int bz = blockIdx.z;
    int m0 = blockIdx.y * 128, n0 = blockIdx.x * 128;
    A += (size_t)bz * sA + (size_t)m0 * lda;
    B += (size_t)bz * sB + (size_t)n0 * ldb;
    int wm = w & 1, wn = w >> 1;

    float acc[4][4][4];
#pragma unroll
    for (int i = 0; i < 4; i++)
#pragma unroll
        for (int j = 0; j < 4; j++)
#pragma unroll
            for (int q = 0; q < 4; q++) acc[i][j][q] = 0.f;

    // cp.async mapping: 512 16B-chunks per tile; thread does chunks 2t, 2t+1
    int r0i = (t * 2) >> 2, c0i = (t * 2) & 3;
    int r1i = (t * 2 + 1) >> 2, c1i = (t * 2 + 1) & 3;

    // ldmatrix base addresses (buffer 0)
    uint32_t aAddr = sbase + (uint32_t)(wm * 64 + (l & 7) + ((l >> 3) & 1) * 8) * 80 + ((l >> 4) * 16);
    int ll = l & 15;
    uint32_t bAddr = sbase + 10240 + (uint32_t)(wn * 32 + (ll & 7)) * 80 + (((ll >> 3) & 1) * 16);

    int nk = K >> 5;
    // prefetch chunk 0 -> buffer 0
    CP16(sbase + r0i * 80 + c0i * 16, A + (size_t)r0i * lda + c0i * 8);
    CP16(sbase + r1i * 80 + c1i * 16, A + (size_t)r1i * lda + c1i * 8);
    CP16(sbase + 10240 + r0i * 80 + c0i * 16, B + (size_t)r0i * ldb + c0i * 8);
    CP16(sbase + 10240 + r1i * 80 + c1i * 16, B + (size_t)r1i * ldb + c1i * 8);
    CPCOMMIT();

    for (int c = 0; c < nk; c++) {
        int s = c & 1;
        if (c + 1 < nk) {
            int k0 = (c + 1) * 32;
            uint32_t bo = (uint32_t)(s ^ 1) * 20480;
            CP16(sbase + bo + r0i * 80 + c0i * 16, A + (size_t)r0i * lda + k0 + c0i * 8);
            CP16(sbase + bo + r1i * 80 + c1i * 16, A + (size_t)r1i * lda + k0 + c1i * 8);
            CP16(sbase + bo + 10240 + r0i * 80 + c0i * 16, B + (size_t)r0i * ldb + k0 + c0i * 8);
            CP16(sbase + bo + 10240 + r1i * 80 + c1i * 16, B + (size_t)r1i * ldb + k0 + c1i * 8);
            CPCOMMIT();
            CPWAIT(1);
        } else {
            CPWAIT(0);
        }
        __syncthreads();

        uint32_t bufoff = (uint32_t)s * 20480;
#pragma unroll
        for (int ks = 0; ks < 2; ks++) {
            uint32_t af[4][4], bf[4][2];
#pragma unroll
            for (int mt = 0; mt < 4; mt++) ldsm_x4(af[mt], aAddr + bufoff + mt * 1280 + ks * 32);
#pragma unroll
            for (int nt = 0; nt < 4; nt++) ldsm_x2(bf[nt], bAddr + bufoff + nt * 640 + ks * 32);
#pragma unroll
            for (int mt = 0; mt < 4; mt++)
#pragma unroll
                for (int nt = 0; nt < 4; nt++) mma16816(acc[mt][nt], af[mt], bf[nt]);
        }
        __syncthreads();
    }

    // ---------------- epilogue ----------------
    int qr = l >> 2, qc = (l & 3) * 2;
    const float* s1 = aux1 ? (aux1 + (size_t)bz * sX1) : nullptr;
    const float INV_M = 1.0f / 1024.0f;
    const float INV_M2 = INV_M * INV_M;

    if (EPI != 3) {
        __nv_bfloat16* C = (__nv_bfloat16*)Cv + (size_t)bz * sC;
#pragma unroll
        for (int mt = 0; mt < 4; mt++) {
            int r0 = m0 + wm * 64 + mt * 16 + qr;
            int r1 = r0 + 8;
            float add0 = 0.f, add1 = 0.f, sr0 = 0.f, sr1 = 0.f;
            if (EPI == 1) { add0 = s1[r0]; add1 = s1[r1]; }
            if (EPI == 2) { sr0 = s1[r0]; sr1 = s1[r1]; }
#pragma unroll
            for (int nt = 0; nt < 4; nt++) {
                int cn = n0 + wn * 32 + nt * 8 + qc;
                float v0 = acc[mt][nt][0], v1 = acc[mt][nt][1];
                float v2 = acc[mt][nt][2], v3 = acc[mt][nt][3];
                if (EPI == 1) { v0 += add0; v1 += add0; v2 += add1; v3 += add1; }
                if (EPI == 2) {
                    float sc0 = s1[cn], sc1 = s1[cn + 1];
                    v0 = (v0 * INV_M - sr0 * sc0 * INV_M2) * 0.0625f;
                    v1 = (v1 * INV_M - sr0 * sc1 * INV_M2) * 0.0625f;
                    v2 = (v2 * INV_M - sr1 * sc0 * INV_M2) * 0.0625f;
                    v3 = (v3 * INV_M - sr1 * sc1 * INV_M2) * 0.0625f;
                }
                *(uint32_t*)&C[(size_t)r0 * ldc + cn] = bf16pack(v0, v1);
                *(uint32_t*)&C[(size_t)r1 * ldc + cn] = bf16pack(v2, v3);
            }
        }
    } else {
        float* C = (float*)Cv + (size_t)bz * sC;
        const float* xr = aux2 + (size_t)bz * sX2;
#pragma unroll
        for (int mt = 0; mt < 4; mt++) {
            int r0 = m0 + wm * 64 + mt * 16 + qr;
            int r1 = r0 + 8;
            float b0 = s1[r0], b1 = s1[r1];
#pragma unroll
            for (int nt = 0; nt < 4; nt++) {
                int cn = n0 + wn * 32 + nt * 8 + qc;
                float2 x0 = *(const float2*)&xr[(size_t)r0 * ldc + cn];
                float2 x1 = *(const float2*)&xr[(size_t)r1 * ldc + cn];
                float2 o0, o1;
                o0.x = acc[mt][nt][0] + b0 + x0.x;
                o0.y = acc[mt][nt][1] + b0 + x0.y;
                o1.x = acc[mt][nt][2] + b1 + x1.x;
                o1.y = acc[mt][nt][3] + b1 + x1.y;
                *(float2*)&C[(size_t)r0 * ldc + cn] = o0;
                *(float2*)&C[(size_t)r1 * ldc + cn] = o1;
            }
        }
    }
}

// ---------------- transpose (any src type -> bf16), per-batch ----------------
template <typename T>
__global__ void transpose_to_bf16(const T* __restrict__ src, __nv_bfloat16* __restrict__ dst,
                                  int R, int Cc, size_t sS, size_t sD) {
    __shared__ float tile[32][33];
    int bz = blockIdx.z;
    src += (size_t)bz * sS;
    dst += (size_t)bz * sD;
    int c0 = blockIdx.x * 32, r0 = blockIdx.y * 32;
    int tx = threadIdx.x, ty = threadIdx.y;
#pragma unroll
    for (int i = ty; i < 32; i += 8)
        tile[i][tx] = (float)src[(size_t)(r0 + i) * Cc + c0 + tx];
    __syncthreads();
#pragma unroll
    for (int i = ty; i < 32; i += 8)
        dst[(size_t)(c0 + i) * R + r0 + tx] = __float2bfloat16(tile[tx][i]);
}

// ---------------- small kernels ----------------
__global__ void pack_weights(const float* __restrict__ Wk, const float* __restrict__ bk,
                             const float* __restrict__ Wv, const float* __restrict__ bv,
                             const float* __restrict__ Wo) {
    int i = blockIdx.x * 256 + threadIdx.x;   // 0..131071
    g_wkv[i] = __float2bfloat16(Wk[i]);
    g_wkv[C2 * CIN + i] = __float2bfloat16(Wv[i]);
    g_wo[i] = __float2bfloat16(Wo[i]);
    if (i < C2) { g_bkv[i] = bk[i]; g_bkv[C2 + i] = bv[i]; }
}

__global__ void rowsum_kernel() {
    int idx = blockIdx.x * 256 + threadIdx.x;  // 32768 rows of kT
    const __nv_bfloat162* p = (const __nv_bfloat162*)(g_kT + (size_t)idx * C2);
    float acc = 0.f;
#pragma unroll 16
    for (int i = 0; i < 128; i++) {
        float2 f = __bfloat1622float2(p[i]);
        acc += f.x + f.y;
    }
    g_s[idx] = acc;
}

__global__ __launch_bounds__(256) void softmax_bf16() {
    size_t row = blockIdx.x;
    __nv_bfloat162* p = (__nv_bfloat162*)(g_attn + row * MM);
    int t = threadIdx.x;
    __nv_bfloat162 a = p[2 * t], b = p[2 * t + 1];
    float2 f0 = __bfloat1622float2(a), f1 = __bfloat1622float2(b);

    __shared__ float red[8];
    __shared__ float bval[2];

    float mx = fmaxf(fmaxf(f0.x, f0.y), fmaxf(f1.x, f1.y));
#pragma unroll
    for (int o = 16; o > 0; o >>= 1) mx = fmaxf(mx, __shfl_xor_sync(0xffffffffu, mx, o));
    if ((t & 31) == 0) red[t >> 5] = mx;
    __syncthreads();
    if (t == 0) {
        float m = red[0];
#pragma unroll
        for (int i = 1; i < 8; i++) m = fmaxf(m, red[i]);
        bval[0] = m;
    }
    __syncthreads();
    mx = bval[0];

    f0.x = __expf(f0.x - mx); f0.y = __expf(f0.y - mx);
    f1.x = __expf(f1.x - mx); f1.y = __expf(f1.y - mx);
    float sm = f0.x + f0.y + f1.x + f1.y;
#pragma unroll
    for (int o = 16; o > 0; o >>= 1) sm += __shfl_xor_sync(0xffffffffu, sm, o);
    __syncthreads();
    if ((t & 31) == 0) red[t >> 5] = sm;
    __syncthreads();
    if (t == 0) {
        float s = 0.f;
#pragma unroll
        for (int i = 0; i < 8; i++) s += red[i];
        bval[1] = 1.f / s;
    }
    __syncthreads();
    float inv = bval[1];
    ((uint32_t*)p)[2 * t] = bf16pack(f0.x * inv, f0.y * inv);
    ((uint32_t*)p)[2 * t + 1] = bf16pack(f1.x * inv, f1.y * inv);
}

// ---------------- launch ----------------
extern "C" void kernel_launch(void* const* d_in, const int* in_sizes, int n_in,
                              void* d_out, int out_size) {
    const float* x = (const float*)d_in[0];
    const float* Wk = (const float*)d_in[1];
    const float* bk = (const float*)d_in[2];
    const float* Wv = (const float*)d_in[3];
    const float* bv = (const float*)d_in[4];
    const float* Wo = (const float*)d_in[5];
    const float* bo = (const float*)d_in[6];
    float* out = (float*)d_out;

    __nv_bfloat16 *xT, *wkv, *wo, *kv, *kT, *vT, *attn, *omid, *projB;
    float *bkv, *s;
    cudaGetSymbolAddress((void**)&xT, g_xT);
    cudaGetSymbolAddress((void**)&wkv, g_wkv);
    cudaGetSymbolAddress((void**)&wo, g_wo);
    cudaGetSymbolAddress((void**)&kv, g_kv);
    cudaGetSymbolAddress((void**)&kT, g_kT);
    cudaGetSymbolAddress((void**)&vT, g_vT);
    cudaGetSymbolAddress((void**)&attn, g_attn);
    cudaGetSymbolAddress((void**)&omid, g_omid);
    cudaGetSymbolAddress((void**)&projB, g_projB);
    cudaGetSymbolAddress((void**)&bkv, g_bkv);
    cudaGetSymbolAddress((void**)&s, g_s);

    dim3 t328(32, 8);

    // 1. weights -> bf16 (+ bias stack)
    pack_weights<<<512, 256>>>(Wk, bk, Wv, bv, Wo);
    // 2. xT[b] = x[b]^T  [1024][512] bf16
    transpose_to_bf16<float><<<dim3(32, 16, 32), t328>>>(x, xT, 512, 1024, 524288, 524288);
    // 3. kv[b][c][m] = Wkv @ x + bkv   (A=wkv rows c, B=xT rows m)
    mma_gemm<1><<<dim3(8, 4, 32), 256>>>(wkv, 512, 0, xT, 512, 524288,
                                         kv, 1024, 524288, 512, bkv, 0, nullptr, 0);
    // 4. kT[b] = k-part^T [1024][256]
    transpose_to_bf16<__nv_bfloat16><<<dim3(32, 8, 32), t328>>>(kv, kT, 256, 1024, 524288, 262144);
    // 5. vT[b] = V^T [256][1024]  (V = v-part memory viewed [1024][256])
    transpose_to_bf16<__nv_bfloat16><<<dim3(8, 32, 32), t328>>>(kv + 262144, vT, 1024, 256, 524288, 262144);
    // 6. s[b][m] = sum_c kT[b][m][c]
    rowsum_kernel<<<128, 256>>>();
    // 7. logits = ((kT kT^T)/M - s s^T/M^2)*c2^-0.5   -> g_attn bf16
    mma_gemm<2><<<dim3(8, 8, 32), 256>>>(kT, 256, 262144, kT, 256, 262144,
                                         attn, 1024, 1048576, 256, s, 1024, nullptr, 0);
    // 8. softmax rows, in place (bf16)
    softmax_bf16<<<32768, 256>>>();
    // 9. omid[b][m][c] = attn @ V   (B = vT rows c)
    mma_gemm<0><<<dim3(2, 8, 32), 256>>>(attn, 1024, 1048576, vT, 1024, 262144,
                                         omid, 256, 262144, 1024, nullptr, 0, nullptr, 0);
    // 10. projB[b] = (omid viewed [256][1024])^T  [1024][256]
    transpose_to_bf16<__nv_bfloat16><<<dim3(32, 8, 32), t328>>>(omid, projB, 256, 1024, 262144, 262144);
    // 11. out = Wo @ Y + bo + x   (A=wo rows o, B=projB rows m), fp32 out
    mma_gemm<3><<<dim3(8, 4, 32), 256>>>(wo, 256, 0, projB, 256, 262144,
                                         out, 1024, 524288, 256, (const float*)bo, 0, x, 524288);
}

// round 4
// speedup vs baseline: 4.2044x; 1.1433x over previous
#include <cuda_runtime.h>
#include <cuda_bf16.h>
#include <cstdint>

#define BN 32
#define CIN 512
#define C2 256
#define MM 1024

// ---------------- scratch (device globals; allocation-free rule) ----------------
__device__ __align__(1024) __nv_bfloat16 g_xT[(size_t)BN * MM * CIN];     // [b][m][in]
__device__ __align__(1024) __nv_bfloat16 g_wk[C2 * CIN];
__device__ __align__(1024) __nv_bfloat16 g_wv[C2 * CIN];
__device__ __align__(1024) __nv_bfloat16 g_wo[CIN * C2];
__device__ __align__(1024) __nv_bfloat16 g_kT[(size_t)BN * MM * C2];      // [b][m][c]
__device__ __align__(1024) __nv_bfloat16 g_v[(size_t)BN * C2 * MM];       // [b][c][m]
__device__ __align__(1024) __nv_bfloat16 g_vT[(size_t)BN * C2 * MM];      // [b][c'][n] = V^T
__device__ float g_s[BN * MM];
__device__ __align__(1024) __nv_bfloat16 g_attn[(size_t)BN * MM * MM];
__device__ __align__(1024) __nv_bfloat16 g_omid[(size_t)BN * MM * C2];    // [b][m][c]
__device__ __align__(1024) __nv_bfloat16 g_projB[(size_t)BN * MM * C2];   // [b][t][c']

// ---------------- helpers ----------------
__device__ __forceinline__ uint32_t smem_u32(const void* p) {
    uint32_t a;
    asm("{ .reg .u64 t; cvta.to.shared.u64 t, %1; cvt.u32.u64 %0, t; }" : "=r"(a) : "l"(p));
    return a;
}
__device__ __forceinline__ uint32_t bf16pack(float lo, float hi) {
    uint32_t r;
    asm("cvt.rn.bf16x2.f32 %0, %1, %2;" : "=r"(r) : "f"(hi), "f"(lo));
    return r;
}
#define CP16(dst, src) \
    asm volatile("cp.async.cg.shared.global [%0], [%1], 16;" :: "r"(dst), "l"(src) : "memory")
#define CPCOMMIT() asm volatile("cp.async.commit_group;" ::: "memory")
#define CPWAIT(n) asm volatile("cp.async.wait_group %0;" :: "n"(n) : "memory")

__device__ __forceinline__ void ldsm_x4(uint32_t* r, uint32_t addr) {
    asm volatile("ldmatrix.sync.aligned.m8n8.x4.shared.b16 {%0,%1,%2,%3}, [%4];"
        : "=r"(r[0]), "=r"(r[1]), "=r"(r[2]), "=r"(r[3]) : "r"(addr));
}
__device__ __forceinline__ void mma16816(float* c, const uint32_t* a, const uint32_t* b) {
    asm volatile("mma.sync.aligned.m16n8k16.row.col.f32.bf16.bf16.f32 "
        "{%0,%1,%2,%3}, {%4,%5,%6,%7}, {%8,%9}, {%0,%1,%2,%3};"
        : "+f"(c[0]), "+f"(c[1]), "+f"(c[2]), "+f"(c[3])
        : "r"(a[0]), "r"(a[1]), "r"(a[2]), "r"(a[3]), "r"(b[0]), "r"(b[1]));
}

#define STG 32768
#define GEMM_SMEM (3 * STG)

// ---------------- HMMA GEMM: 128x128 CTA tile, BK=64, 3-stage cp.async ----------------
// D[i][j] = sum_k A[m0+i][k] * B[n0+j][k]; A,B K-major bf16.
// Smem: per stage A(16KB)+B(16KB); rows 128B, XOR swizzle chunk^(row&7).
// EPI: 0 none (bf16), 1 +aux1[row] (bf16), 2 cov transform (bf16),
//      3 +aux1[row]+aux2 residual (fp32), 4 +aux1[col] (bf16)
template <int EPI>
__global__ __launch_bounds__(256, 2)
void mma_gemm(const __nv_bfloat16* __restrict__ A, int lda, size_t sA,
              const __nv_bfloat16* __restrict__ B, int ldb, size_t sB,
              void* __restrict__ Cv, int ldc, size_t sC, int K,
              const float* __restrict__ aux1, size_t sX1,
              const float* __restrict__ aux2, size_t sX2) {
    extern __shared__ __align__(128) char smem[];
    uint32_t sbase = smem_u32(smem);
    int t = threadIdx.x, l = t & 31, w = t >> 5;
    int bz = blockIdx.z;
    int m0 = blockIdx.y * 128, n0 = blockIdx.x * 128;
    A += (size_t)bz * sA + (size_t)m0 * lda;
    B += (size_t)bz * sB + (size_t)n0 * ldb;
    int wm = w & 1, wn = w >> 1;

    float acc[4][4][4];
#pragma unroll
    for (int i = 0; i < 4; i++)
#pragma unroll
        for (int j = 0; j < 4; j++)
#pragma unroll
            for (int q = 0; q < 4; q++) acc[i][j][q] = 0.f;

    // producer chunk mapping: thread does 4 A-chunks and 4 B-chunks per stage
    int pidx = t * 4;
    int prow = pidx >> 3, pch0 = pidx & 7;   // 4 consecutive chunks, same row (8 chunks/row)
    // consumer bases
    int la = (l & 7) + ((l >> 3) & 1) * 8;
    int akb = l >> 4;                         // A k-half select
    uint32_t aRow = (uint32_t)(wm * 64 + la) * 128;
    int bkb = (l >> 3) & 1;                   // B k-half select
    uint32_t bRow = 16384u + (uint32_t)(wn * 32 + ((l >> 4) << 3) + (l & 7)) * 128;
    int swz = l & 7;
    int pswz = prow & 7;

    int nk = K >> 6;
    // prologue: prefetch stages 0,1
#pragma unroll
    for (int c = 0; c < 2; c++) {
        uint32_t so = (uint32_t)c * STG;
        int k0 = c * 64;
#pragma unroll
        for (int q = 0; q < 4; q++) {
            int ch = pch0 + q;
            uint32_t po = so + (uint32_t)prow * 128 + (uint32_t)((ch ^ pswz) << 4);
            CP16(po + sbase, A + (size_t)prow * lda + k0 + ch * 8);
            CP16(po + sbase + 16384, B + (size_t)prow * ldb + k0 + ch * 8);
        }
        CPCOMMIT();
    }

    for (int c = 0; c < nk; c++) {
        if (c + 1 < nk) { CPWAIT(1); } else { CPWAIT(0); }
        __syncthreads();
        if (c + 2 < nk) {
            int cs = c + 2;
            uint32_t so = (uint32_t)(cs % 3) * STG;
            int k0 = cs * 64;
#pragma unroll
            for (int q = 0; q < 4; q++) {
                int ch = pch0 + q;
                uint32_t po = so + (uint32_t)prow * 128 + (uint32_t)((ch ^ pswz) << 4);
                CP16(po + sbase, A + (size_t)prow * lda + k0 + ch * 8);
                CP16(po + sbase + 16384, B + (size_t)prow * ldb + k0 + ch * 8);
            }
            CPCOMMIT();
        }
        uint32_t so = sbase + (uint32_t)(c % 3) * STG;
#pragma unroll
        for (int ks = 0; ks < 4; ks++) {
            uint32_t af[4][4], bfr[2][4];
            uint32_t aoff = (uint32_t)(((ks * 2 + akb) ^ swz) << 4);
#pragma unroll
            for (int mt = 0; mt < 4; mt++)
                ldsm_x4(af[mt], so + aRow + (uint32_t)mt * 2048 + aoff);
            uint32_t boff = (uint32_t)(((ks * 2 + bkb) ^ swz) << 4);
#pragma unroll
            for (int np = 0; np < 2; np++)
                ldsm_x4(bfr[np], so + bRow + (uint32_t)np * 2048 + boff);
#pragma unroll
            for (int mt = 0; mt < 4; mt++) {
                mma16816(acc[mt][0], af[mt], &bfr[0][0]);
                mma16816(acc[mt][1], af[mt], &bfr[0][2]);
                mma16816(acc[mt][2], af[mt], &bfr[1][0]);
                mma16816(acc[mt][3], af[mt], &bfr[1][2]);
            }
        }
    }

    // ---------------- epilogue ----------------
    int qr = l >> 2, qc = (l & 3) * 2;
    const float* s1 = aux1 ? (aux1 + (size_t)bz * sX1) : nullptr;
    const float INV_M = 1.0f / 1024.0f;
    const float INV_M2 = INV_M * INV_M;

    if (EPI != 3) {
        __nv_bfloat16* C = (__nv_bfloat16*)Cv + (size_t)bz * sC;
#pragma unroll
        for (int mt = 0; mt < 4; mt++) {
            int r0 = m0 + wm * 64 + mt * 16 + qr;
            int r1 = r0 + 8;
            float add0 = 0.f, add1 = 0.f, sr0 = 0.f, sr1 = 0.f;
            if (EPI == 1) { add0 = s1[r0]; add1 = s1[r1]; }
            if (EPI == 2) { sr0 = s1[r0]; sr1 = s1[r1]; }
#pragma unroll
            for (int nt = 0; nt < 4; nt++) {
                int cn = n0 + wn * 32 + nt * 8 + qc;
                float v0 = acc[mt][nt][0], v1 = acc[mt][nt][1];
                float v2 = acc[mt][nt][2], v3 = acc[mt][nt][3];
                if (EPI == 1) { v0 += add0; v1 += add0; v2 += add1; v3 += add1; }
                if (EPI == 4) {
                    float sc0 = s1[cn], sc1 = s1[cn + 1];
                    v0 += sc0; v1 += sc1; v2 += sc0; v3 += sc1;
                }
                if (EPI == 2) {
                    float sc0 = s1[cn], sc1 = s1[cn + 1];
                    v0 = (v0 * INV_M - sr0 * sc0 * INV_M2) * 0.0625f;
                    v1 = (v1 * INV_M - sr0 * sc1 * INV_M2) * 0.0625f;
                    v2 = (v2 * INV_M - sr1 * sc0 * INV_M2) * 0.0625f;
                    v3 = (v3 * INV_M - sr1 * sc1 * INV_M2) * 0.0625f;
                }
                *(uint32_t*)&C[(size_t)r0 * ldc + cn] = bf16pack(v0, v1);
                *(uint32_t*)&C[(size_t)r1 * ldc + cn] = bf16pack(v2, v3);
            }
        }
    } else {
        float* C = (float*)Cv + (size_t)bz * sC;
        const float* xr = aux2 + (size_t)bz * sX2;
#pragma unroll
        for (int mt = 0; mt < 4; mt++) {
            int r0 = m0 + wm * 64 + mt * 16 + qr;
            int r1 = r0 + 8;
            float b0 = s1[r0], b1 = s1[r1];
#pragma unroll
            for (int nt = 0; nt < 4; nt++) {
                int cn = n0 + wn * 32 + nt * 8 + qc;
                float2 x0 = *(const float2*)&xr[(size_t)r0 * ldc + cn];
                float2 x1 = *(const float2*)&xr[(size_t)r1 * ldc + cn];
                float2 o0, o1;
                o0.x = acc[mt][nt][0] + b0 + x0.x;
                o0.y = acc[mt][nt][1] + b0 + x0.y;
                o1.x = acc[mt][nt][2] + b1 + x1.x;
                o1.y = acc[mt][nt][3] + b1 + x1.y;
                *(float2*)&C[(size_t)r0 * ldc + cn] = o0;
                *(float2*)&C[(size_t)r1 * ldc + cn] = o1;
            }
        }
    }
}

// ---------------- transpose (any src type -> bf16), per-batch ----------------
template <typename T>
__global__ void transpose_to_bf16(const T* __restrict__ src, __nv_bfloat16* __restrict__ dst,
                                  int R, int Cc, size_t sS, size_t sD) {
    __shared__ float tile[32][33];
    int bz = blockIdx.z;
    src += (size_t)bz * sS;
    dst += (size_t)bz * sD;
    int c0 = blockIdx.x * 32, r0 = blockIdx.y * 32;
    int tx = threadIdx.x, ty = threadIdx.y;
#pragma unroll
    for (int i = ty; i < 32; i += 8)
        tile[i][tx] = (float)src[(size_t)(r0 + i) * Cc + c0 + tx];
    __syncthreads();
#pragma unroll
    for (int i = ty; i < 32; i += 8)
        dst[(size_t)(c0 + i) * R + r0 + tx] = __float2bfloat16(tile[tx][i]);
}

// ---------------- small kernels ----------------
__global__ void pack_weights(const float* __restrict__ Wk, const float* __restrict__ Wv,
                             const float* __restrict__ Wo) {
    int i = blockIdx.x * 256 + threadIdx.x;   // 0..131071
    g_wk[i] = __float2bfloat16(Wk[i]);
    g_wv[i] = __float2bfloat16(Wv[i]);
    g_wo[i] = __float2bfloat16(Wo[i]);
}

__global__ void rowsum_kernel() {
    int idx = blockIdx.x * 256 + threadIdx.x;  // 32768 rows of kT
    const __nv_bfloat162* p = (const __nv_bfloat162*)(g_kT + (size_t)idx * C2);
    float acc = 0.f;
#pragma unroll 16
    for (int i = 0; i < 128; i++) {
        float2 f = __bfloat1622float2(p[i]);
        acc += f.x + f.y;
    }
    g_s[idx] = acc;
}

__global__ __launch_bounds__(256) void softmax_bf16() {
    size_t row = blockIdx.x;
    __nv_bfloat162* p = (__nv_bfloat162*)(g_attn + row * MM);
    int t = threadIdx.x;
    __nv_bfloat162 a = p[2 * t], b = p[2 * t + 1];
    float2 f0 = __bfloat1622float2(a), f1 = __bfloat1622float2(b);

    __shared__ float red[8];
    __shared__ float bval[2];

    float mx = fmaxf(fmaxf(f0.x, f0.y), fmaxf(f1.x, f1.y));
#pragma unroll
    for (int o = 16; o > 0; o >>= 1) mx = fmaxf(mx, __shfl_xor_sync(0xffffffffu, mx, o));
    if ((t & 31) == 0) red[t >> 5] = mx;
    __syncthreads();
    if (t == 0) {
        float m = red[0];
#pragma unroll
        for (int i = 1; i < 8; i++) m = fmaxf(m, red[i]);
        bval[0] = m;
    }
    __syncthreads();
    mx = bval[0];

    f0.x = __expf(f0.x - mx); f0.y = __expf(f0.y - mx);
    f1.x = __expf(f1.x - mx); f1.y = __expf(f1.y - mx);
    float sm = f0.x + f0.y + f1.x + f1.y;
#pragma unroll
    for (int o = 16; o > 0; o >>= 1) sm += __shfl_xor_sync(0xffffffffu, sm, o);
    __syncthreads();
    if ((t & 31) == 0) red[t >> 5] = sm;
    __syncthreads();
    if (t == 0) {
        float s = 0.f;
#pragma unroll
        for (int i = 0; i < 8; i++) s += red[i];
        bval[1] = 1.f / s;
    }
    __syncthreads();
    float inv = bval[1];
    ((uint32_t*)p)[2 * t] = bf16pack(f0.x * inv, f0.y * inv);
    ((uint32_t*)p)[2 * t + 1] = bf16pack(f1.x * inv, f1.y * inv);
}

// ---------------- launch ----------------
extern "C" void kernel_launch(void* const* d_in, const int* in_sizes, int n_in,
                              void* d_out, int out_size) {
    const float* x = (const float*)d_in[0];
    const float* Wk = (const float*)d_in[1];
    const float* bk = (const float*)d_in[2];
    const float* Wv = (const float*)d_in[3];
    const float* bv = (const float*)d_in[4];
    const float* Wo = (const float*)d_in[5];
    const float* bo = (const float*)d_in[6];
    float* out = (float*)d_out;

    __nv_bfloat16 *xT, *wk, *wv, *wo, *kT, *v, *vT, *attn, *omid, *projB;
    float* s;
    cudaGetSymbolAddress((void**)&xT, g_xT);
    cudaGetSymbolAddress((void**)&wk, g_wk);
    cudaGetSymbolAddress((void**)&wv, g_wv);
    cudaGetSymbolAddress((void**)&wo, g_wo);
    cudaGetSymbolAddress((void**)&kT, g_kT);
    cudaGetSymbolAddress((void**)&v, g_v);
    cudaGetSymbolAddress((void**)&vT, g_vT);
    cudaGetSymbolAddress((void**)&attn, g_attn);
    cudaGetSymbolAddress((void**)&omid, g_omid);
    cudaGetSymbolAddress((void**)&projB, g_projB);
    cudaGetSymbolAddress((void**)&s, g_s);

    cudaFuncSetAttribute(mma_gemm<0>, cudaFuncAttributeMaxDynamicSharedMemorySize, GEMM_SMEM);
    cudaFuncSetAttribute(mma_gemm<1>, cudaFuncAttributeMaxDynamicSharedMemorySize, GEMM_SMEM);
    cudaFuncSetAttribute(mma_gemm<2>, cudaFuncAttributeMaxDynamicSharedMemorySize, GEMM_SMEM);
    cudaFuncSetAttribute(mma_gemm<3>, cudaFuncAttributeMaxDynamicSharedMemorySize, GEMM_SMEM);
    cudaFuncSetAttribute(mma_gemm<4>, cudaFuncAttributeMaxDynamicSharedMemorySize, GEMM_SMEM);

    dim3 t328(32, 8);

    // 1. weights -> bf16
    pack_weights<<<512, 256>>>(Wk, Wv, Wo);
    // 2. xT[b] = x[b]^T  [1024][512] bf16
    transpose_to_bf16<float><<<dim3(32, 16, 32), t328>>>(x, xT, 512, 1024, 524288, 524288);
    // 3a. kT[b][m][c] = xT @ Wk^T + bk[col]
    mma_gemm<4><<<dim3(2, 8, 32), 256, GEMM_SMEM>>>(xT, 512, 524288, wk, 512, 0,
                                                    kT, 256, 262144, 512, bk, 0, nullptr, 0);
    // 3b. v[b][c][m] = Wv @ x + bv[row]
    mma_gemm<1><<<dim3(8, 2, 32), 256, GEMM_SMEM>>>(wv, 512, 0, xT, 512, 524288,
                                                    v, 1024, 262144, 512, bv, 0, nullptr, 0);
    // 4. vT[b] = (v viewed [1024][256])^T -> [256][1024]
    transpose_to_bf16<__nv_bfloat16><<<dim3(8, 32, 32), t328>>>(v, vT, 1024, 256, 262144, 262144);
    // 5. s[b][m] = sum_c kT[b][m][c]
    rowsum_kernel<<<128, 256>>>();
    // 6. logits = ((kT kT^T)/M - s s^T/M^2)*c2^-0.5 -> attn bf16
    mma_gemm<2><<<dim3(8, 8, 32), 256, GEMM_SMEM>>>(kT, 256, 262144, kT, 256, 262144,
                                                    attn, 1024, 1048576, 256, s, 1024, nullptr, 0);
    // 7. softmax rows in place
    softmax_bf16<<<32768, 256>>>();
    // 8. omid[b][m][c] = attn @ V   (B = vT rows c')
    mma_gemm<0><<<dim3(2, 8, 32), 256, GEMM_SMEM>>>(attn, 1024, 1048576, vT, 1024, 262144,
                                                    omid, 256, 262144, 1024, nullptr, 0, nullptr, 0);
    // 9. projB[b] = (omid viewed [256][1024])^T -> [1024][256]
    transpose_to_bf16<__nv_bfloat16><<<dim3(32, 8, 32), t328>>>(omid, projB, 256, 1024, 262144, 262144);
    // 10. out = Wo @ Y + bo + x   (fp32 out)
    mma_gemm<3><<<dim3(8, 4, 32), 256, GEMM_SMEM>>>(wo, 256, 0, projB, 256, 262144,
                                                    out, 1024, 524288, 256, bo, 0, x, 524288);
}

// round 5
// speedup vs baseline: 4.6169x; 1.0981x over previous
#include <cuda_runtime.h>
#include <cuda_bf16.h>
#include <cstdint>

#define BN 32
#define CIN 512
#define C2 256
#define MM 1024

// ---------------- scratch (device globals; allocation-free rule) ----------------
__device__ __align__(1024) __nv_bfloat16 g_xT[(size_t)BN * MM * CIN];     // [b][m][in]
__device__ __align__(1024) __nv_bfloat16 g_wk[C2 * CIN];
__device__ __align__(1024) __nv_bfloat16 g_wv[C2 * CIN];
__device__ __align__(1024) __nv_bfloat16 g_wo[CIN * C2];
__device__ __align__(1024) __nv_bfloat16 g_kT[(size_t)BN * MM * C2];      // [b][m][c]
__device__ __align__(1024) __nv_bfloat16 g_v[(size_t)BN * C2 * MM];       // [b][c][m]
__device__ __align__(1024) __nv_bfloat16 g_vT[(size_t)BN * C2 * MM];      // [b][c'][n] = V^T
__device__ float g_s[BN * MM];                                            // channel sums of k
__device__ float g_z[BN * MM];                                            // softmax denominators
__device__ __align__(1024) __nv_bfloat16 g_attn[(size_t)BN * MM * MM];    // exp(logits), unnormalized
__device__ __align__(1024) __nv_bfloat16 g_omid[(size_t)BN * MM * C2];    // [b][m][c]
__device__ __align__(1024) __nv_bfloat16 g_projB[(size_t)BN * MM * C2];   // [b][t][c']

// ---------------- helpers ----------------
__device__ __forceinline__ uint32_t smem_u32(const void* p) {
    uint32_t a;
    asm("{ .reg .u64 t; cvta.to.shared.u64 t, %1; cvt.u32.u64 %0, t; }" : "=r"(a) : "l"(p));
    return a;
}
__device__ __forceinline__ uint32_t bf16pack(float lo, float hi) {
    uint32_t r;
    asm("cvt.rn.bf16x2.f32 %0, %1, %2;" : "=r"(r) : "f"(hi), "f"(lo));
    return r;
}
#define CP16(dst, src) \
    asm volatile("cp.async.cg.shared.global [%0], [%1], 16;" :: "r"(dst), "l"(src) : "memory")
#define CPCOMMIT() asm volatile("cp.async.commit_group;" ::: "memory")
#define CPWAIT(n) asm volatile("cp.async.wait_group %0;" :: "n"(n) : "memory")

__device__ __forceinline__ void ldsm_x4(uint32_t* r, uint32_t addr) {
    asm volatile("ldmatrix.sync.aligned.m8n8.x4.shared.b16 {%0,%1,%2,%3}, [%4];"
        : "=r"(r[0]), "=r"(r[1]), "=r"(r[2]), "=r"(r[3]) : "r"(addr));
}
__device__ __forceinline__ void mma16816(float* c, const uint32_t* a, const uint32_t* b) {
    asm volatile("mma.sync.aligned.m16n8k16.row.col.f32.bf16.bf16.f32 "
        "{%0,%1,%2,%3}, {%4,%5,%6,%7}, {%8,%9}, {%0,%1,%2,%3};"
        : "+f"(c[0]), "+f"(c[1]), "+f"(c[2]), "+f"(c[3])
        : "r"(a[0]), "r"(a[1]), "r"(a[2]), "r"(a[3]), "r"(b[0]), "r"(b[1]));
}

#define STG 32768
#define GEMM_SMEM (3 * STG)

// ---------------- HMMA GEMM: 128x128 CTA tile, BK=64, 3-stage cp.async ----------------
// D[i][j] = sum_k A[m0+i][k] * B[n0+j][k]; A,B K-major bf16.
// EPI: 0 none (bf16)
//      1 +aux1[row] (bf16)
//      2 cov transform + exp, atomic row-sums into aux2 (bf16 out)
//      3 +aux1[row]+aux2 residual (fp32 out)
//      4 +aux1[col], atomic row-sums into aux2 (bf16 out)
//      5 *(1/aux1[row]) (bf16 out)
template <int EPI>
__global__ __launch_bounds__(256, 2)
void mma_gemm(const __nv_bfloat16* __restrict__ A, int lda, size_t sA,
              const __nv_bfloat16* __restrict__ B, int ldb, size_t sB,
              void* __restrict__ Cv, int ldc, size_t sC, int K,
              const float* __restrict__ aux1, size_t sX1,
              const float* __restrict__ aux2, size_t sX2) {
    extern __shared__ __align__(128) char smem[];
    uint32_t sbase = smem_u32(smem);
    int t = threadIdx.x, l = t & 31, w = t >> 5;
    int bz = blockIdx.z;
    int m0 = blockIdx.y * 128, n0 = blockIdx.x * 128;
    A += (size_t)bz * sA + (size_t)m0 * lda;
    B += (size_t)bz * sB + (size_t)n0 * ldb;
    int wm = w & 1, wn = w >> 1;

    float acc[4][4][4];
#pragma unroll
    for (int i = 0; i < 4; i++)
#pragma unroll
        for (int j = 0; j < 4; j++)
#pragma unroll
            for (int q = 0; q < 4; q++) acc[i][j][q] = 0.f;

    int pidx = t * 4;
    int prow = pidx >> 3, pch0 = pidx & 7;
    int la = (l & 7) + ((l >> 3) & 1) * 8;
    int akb = l >> 4;
    uint32_t aRow = (uint32_t)(wm * 64 + la) * 128;
    int bkb = (l >> 3) & 1;
    uint32_t bRow = 16384u + (uint32_t)(wn * 32 + ((l >> 4) << 3) + (l & 7)) * 128;
    int swz = l & 7;
    int pswz = prow & 7;

    int nk = K >> 6;
#pragma unroll
    for (int c = 0; c < 2; c++) {
        uint32_t so = (uint32_t)c * STG;
        int k0 = c * 64;
#pragma unroll
        for (int q = 0; q < 4; q++) {
            int ch = pch0 + q;
            uint32_t po = so + (uint32_t)prow * 128 + (uint32_t)((ch ^ pswz) << 4);
            CP16(po + sbase, A + (size_t)prow * lda + k0 + ch * 8);
            CP16(po + sbase + 16384, B + (size_t)prow * ldb + k0 + ch * 8);
        }
        CPCOMMIT();
    }

    for (int c = 0; c < nk; c++) {
        if (c + 1 < nk) { CPWAIT(1); } else { CPWAIT(0); }
        __syncthreads();
        if (c + 2 < nk) {
            int cs = c + 2;
            uint32_t so = (uint32_t)(cs % 3) * STG;
            int k0 = cs * 64;
#pragma unroll
            for (int q = 0; q < 4; q++) {
                int ch = pch0 + q;
                uint32_t po = so + (uint32_t)prow * 128 + (uint32_t)((ch ^ pswz) << 4);
                CP16(po + sbase, A + (size_t)prow * lda + k0 + ch * 8);
                CP16(po + sbase + 16384, B + (size_t)prow * ldb + k0 + ch * 8);
            }
            CPCOMMIT();
        }
        uint32_t so = sbase + (uint32_t)(c % 3) * STG;
#pragma unroll
        for (int ks = 0; ks < 4; ks++) {
            uint32_t af[4][4], bfr[2][4];
            uint32_t aoff = (uint32_t)(((ks * 2 + akb) ^ swz) << 4);
#pragma unroll
            for (int mt = 0; mt < 4; mt++)
                ldsm_x4(af[mt], so + aRow + (uint32_t)mt * 2048 + aoff);
            uint32_t boff = (uint32_t)(((ks * 2 + bkb) ^ swz) << 4);
#pragma unroll
            for (int np = 0; np < 2; np++)
                ldsm_x4(bfr[np], so + bRow + (uint32_t)np * 2048 + boff);
#pragma unroll
            for (int mt = 0; mt < 4; mt++) {
                mma16816(acc[mt][0], af[mt], &bfr[0][0]);
                mma16816(acc[mt][1], af[mt], &bfr[0][2]);
                mma16816(acc[mt][2], af[mt], &bfr[1][0]);
                mma16816(acc[mt][3], af[mt], &bfr[1][2]);
            }
        }
    }

    // ---------------- epilogue ----------------
    int qr = l >> 2, qc = (l & 3) * 2;
    const float* s1 = aux1 ? (aux1 + (size_t)bz * sX1) : nullptr;
    const float INV_M = 1.0f / 1024.0f;
    const float INV_M2 = INV_M * INV_M;

    if (EPI != 3) {
        __nv_bfloat16* C = (__nv_bfloat16*)Cv + (size_t)bz * sC;
        float* zout = (EPI == 2 || EPI == 4) ? ((float*)aux2 + (size_t)bz * sX2) : nullptr;
#pragma unroll
        for (int mt = 0; mt < 4; mt++) {
            int r0 = m0 + wm * 64 + mt * 16 + qr;
            int r1 = r0 + 8;
            float add0 = 0.f, add1 = 0.f, sr0 = 0.f, sr1 = 0.f;
            if (EPI == 1) { add0 = s1[r0]; add1 = s1[r1]; }
            if (EPI == 2) { sr0 = s1[r0]; sr1 = s1[r1]; }
            if (EPI == 5) { add0 = __frcp_rn(s1[r0]); add1 = __frcp_rn(s1[r1]); }
            float p0 = 0.f, p1 = 0.f;   // row-sum partials (EPI 2/4)
#pragma unroll
            for (int nt = 0; nt < 4; nt++) {
                int cn = n0 + wn * 32 + nt * 8 + qc;
                float v0 = acc[mt][nt][0], v1 = acc[mt][nt][1];
                float v2 = acc[mt][nt][2], v3 = acc[mt][nt][3];
                if (EPI == 1) { v0 += add0; v1 += add0; v2 += add1; v3 += add1; }
                if (EPI == 5) { v0 *= add0; v1 *= add0; v2 *= add1; v3 *= add1; }
                if (EPI == 4) {
                    float sc0 = s1[cn], sc1 = s1[cn + 1];
                    v0 += sc0; v1 += sc1; v2 += sc0; v3 += sc1;
                    p0 += v0 + v1; p1 += v2 + v3;
                }
                if (EPI == 2) {
                    float sc0 = s1[cn], sc1 = s1[cn + 1];
                    v0 = __expf((v0 * INV_M - sr0 * sc0 * INV_M2) * 0.0625f);
                    v1 = __expf((v1 * INV_M - sr0 * sc1 * INV_M2) * 0.0625f);
                    v2 = __expf((v2 * INV_M - sr1 * sc0 * INV_M2) * 0.0625f);
                    v3 = __expf((v3 * INV_M - sr1 * sc1 * INV_M2) * 0.0625f);
                    p0 += v0 + v1; p1 += v2 + v3;
                }
                *(uint32_t*)&C[(size_t)r0 * ldc + cn] = bf16pack(v0, v1);
                *(uint32_t*)&C[(size_t)r1 * ldc + cn] = bf16pack(v2, v3);
            }
            if (EPI == 2 || EPI == 4) {
                p0 += __shfl_xor_sync(0xffffffffu, p0, 1);
                p0 += __shfl_xor_sync(0xffffffffu, p0, 2);
                p1 += __shfl_xor_sync(0xffffffffu, p1, 1);
                p1 += __shfl_xor_sync(0xffffffffu, p1, 2);
                if ((l & 3) == 0) {
                    atomicAdd(&zout[r0], p0);
                    atomicAdd(&zout[r1], p1);
                }
            }
        }
    } else {
        float* C = (float*)Cv + (size_t)bz * sC;
        const float* xr = aux2 + (size_t)bz * sX2;
#pragma unroll
        for (int mt = 0; mt < 4; mt++) {
            int r0 = m0 + wm * 64 + mt * 16 + qr;
            int r1 = r0 + 8;
            float b0 = s1[r0], b1 = s1[r1];
#pragma unroll
            for (int nt = 0; nt < 4; nt++) {
                int cn = n0 + wn * 32 + nt * 8 + qc;
                float2 x0 = *(const float2*)&xr[(size_t)r0 * ldc + cn];
                float2 x1 = *(const float2*)&xr[(size_t)r1 * ldc + cn];
                float2 o0, o1;
                o0.x = acc[mt][nt][0] + b0 + x0.x;
                o0.y = acc[mt][nt][1] + b0 + x0.y;
                o1.x = acc[mt][nt][2] + b1 + x1.x;
                o1.y = acc[mt][nt][3] + b1 + x1.y;
                *(float2*)&C[(size_t)r0 * ldc + cn] = o0;
                *(float2*)&C[(size_t)r1 * ldc + cn] = o1;
            }
        }
    }
}

// ---------------- transpose (any src type -> bf16), per-batch ----------------
template <typename T>
__global__ void transpose_to_bf16(const T* __restrict__ src, __nv_bfloat16* __restrict__ dst,
                                  int R, int Cc, size_t sS, size_t sD) {
    __shared__ float tile[32][33];
    int bz = blockIdx.z;
    src += (size_t)bz * sS;
    dst += (size_t)bz * sD;
    int c0 = blockIdx.x * 32, r0 = blockIdx.y * 32;
    int tx = threadIdx.x, ty = threadIdx.y;
#pragma unroll
    for (int i = ty; i < 32; i += 8)
        tile[i][tx] = (float)src[(size_t)(r0 + i) * Cc + c0 + tx];
    __syncthreads();
#pragma unroll
    for (int i = ty; i < 32; i += 8)
        dst[(size_t)(c0 + i) * R + r0 + tx] = __float2bfloat16(tile[tx][i]);
}

// ---------------- small kernels ----------------
__global__ void pack_weights(const float* __restrict__ Wk, const float* __restrict__ Wv,
                             const float* __restrict__ Wo) {
    int i = blockIdx.x * 256 + threadIdx.x;   // 0..131071
    g_wk[i] = __float2bfloat16(Wk[i]);
    g_wv[i] = __float2bfloat16(Wv[i]);
    g_wo[i] = __float2bfloat16(Wo[i]);
}

__global__ void zero_sums() {
    int i = blockIdx.x * 256 + threadIdx.x;   // 0..32767
    g_s[i] = 0.f;
    g_z[i] = 0.f;
}

// ---------------- launch ----------------
extern "C" void kernel_launch(void* const* d_in, const int* in_sizes, int n_in,
                              void* d_out, int out_size) {
    const float* x = (const float*)d_in[0];
    const float* Wk = (const float*)d_in[1];
    const float* bk = (const float*)d_in[2];
    const float* Wv = (const float*)d_in[3];
    const float* bv = (const float*)d_in[4];
    const float* Wo = (const float*)d_in[5];
    const float* bo = (const float*)d_in[6];
    float* out = (float*)d_out;

    __nv_bfloat16 *xT, *wk, *wv, *wo, *kT, *v, *vT, *attn, *omid, *projB;
    float *s, *z;
    cudaGetSymbolAddress((void**)&xT, g_xT);
    cudaGetSymbolAddress((void**)&wk, g_wk);
    cudaGetSymbolAddress((void**)&wv, g_wv);
    cudaGetSymbolAddress((void**)&wo, g_wo);
    cudaGetSymbolAddress((void**)&kT, g_kT);
    cudaGetSymbolAddress((void**)&v, g_v);
    cudaGetSymbolAddress((void**)&vT, g_vT);
    cudaGetSymbolAddress((void**)&attn, g_attn);
    cudaGetSymbolAddress((void**)&omid, g_omid);
    cudaGetSymbolAddress((void**)&projB, g_projB);
    cudaGetSymbolAddress((void**)&s, g_s);
    cudaGetSymbolAddress((void**)&z, g_z);

    cudaFuncSetAttribute(mma_gemm<0>, cudaFuncAttributeMaxDynamicSharedMemorySize, GEMM_SMEM);
    cudaFuncSetAttribute(mma_gemm<1>, cudaFuncAttributeMaxDynamicSharedMemorySize, GEMM_SMEM);
    cudaFuncSetAttribute(mma_gemm<2>, cudaFuncAttributeMaxDynamicSharedMemorySize, GEMM_SMEM);
    cudaFuncSetAttribute(mma_gemm<3>, cudaFuncAttributeMaxDynamicSharedMemorySize, GEMM_SMEM);
    cudaFuncSetAttribute(mma_gemm<4>, cudaFuncAttributeMaxDynamicSharedMemorySize, GEMM_SMEM);
    cudaFuncSetAttribute(mma_gemm<5>, cudaFuncAttributeMaxDynamicSharedMemorySize, GEMM_SMEM);

    dim3 t328(32, 8);

    // 1. weights -> bf16; zero accumulators
    pack_weights<<<512, 256>>>(Wk, Wv, Wo);
    zero_sums<<<128, 256>>>();
    // 2. xT[b] = x[b]^T  [1024][512] bf16
    transpose_to_bf16<float><<<dim3(32, 16, 32), t328>>>(x, xT, 512, 1024, 524288, 524288);
    // 3a. kT[b][m][c] = xT @ Wk^T + bk[col]; s[m] accumulated via atomics
    mma_gemm<4><<<dim3(2, 8, 32), 256, GEMM_SMEM>>>(xT, 512, 524288, wk, 512, 0,
                                                    kT, 256, 262144, 512, bk, 0, s, 1024);
    // 3b. v[b][c][m] = Wv @ x + bv[row]
    mma_gemm<1><<<dim3(8, 2, 32), 256, GEMM_SMEM>>>(wv, 512, 0, xT, 512, 524288,
                                                    v, 1024, 262144, 512, bv, 0, nullptr, 0);
    // 4. vT[b] = (v viewed [1024][256])^T -> [256][1024]
    transpose_to_bf16<__nv_bfloat16><<<dim3(8, 32, 32), t328>>>(v, vT, 1024, 256, 262144, 262144);
    // 5. attn = exp(((kT kT^T)/M - s s^T/M^2)*c2^-0.5); z[m] = row sums (atomics)
    mma_gemm<2><<<dim3(8, 8, 32), 256, GEMM_SMEM>>>(kT, 256, 262144, kT, 256, 262144,
                                                    attn, 1024, 1048576, 256, s, 1024, z, 1024);
    // 6. omid[b][m][c] = (attn @ V) / z[m]
    mma_gemm<5><<<dim3(2, 8, 32), 256, GEMM_SMEM>>>(attn, 1024, 1048576, vT, 1024, 262144,
                                                    omid, 256, 262144, 1024, z, 1024, nullptr, 0);
    // 7. projB[b] = (omid viewed [256][1024])^T -> [1024][256]
    transpose_to_bf16<__nv_bfloat16><<<dim3(32, 8, 32), t328>>>(omid, projB, 256, 1024, 262144, 262144);
    // 8. out = Wo @ Y + bo + x   (fp32 out)
    mma_gemm<3><<<dim3(8, 4, 32), 256, GEMM_SMEM>>>(wo, 256, 0, projB, 256, 262144,
                                                    out, 1024, 524288, 256, bo, 0, x, 524288);
}

// round 6
// speedup vs baseline: 5.4211x; 1.1742x over previous
#include <cuda_runtime.h>
#include <cuda_bf16.h>
#include <cstdint>

#define BN 32
#define CIN 512
#define C2 256
#define MM 1024

// ---------------- scratch (device globals; allocation-free rule) ----------------
__device__ __align__(1024) __nv_bfloat16 g_xT[(size_t)BN * MM * CIN];     // [b][m][in]
__device__ __align__(1024) __nv_bfloat16 g_wk[C2 * CIN];
__device__ __align__(1024) __nv_bfloat16 g_wv[C2 * CIN];
__device__ __align__(1024) __nv_bfloat16 g_wo[CIN * C2];
__device__ __align__(1024) __nv_bfloat16 g_kT[(size_t)BN * MM * C2];      // [b][m][c]
__device__ __align__(1024) __nv_bfloat16 g_v[(size_t)BN * C2 * MM];       // [b][c][m]
__device__ __align__(1024) __nv_bfloat16 g_vT[(size_t)BN * C2 * MM];      // [b][c'][n] = V^T
__device__ float g_s[BN * MM];                                            // channel sums of k
__device__ float g_z[BN * MM];                                            // softmax denominators
__device__ __align__(1024) __nv_bfloat16 g_attn[(size_t)BN * MM * MM];    // exp(logits), unnormalized
__device__ __align__(1024) __nv_bfloat16 g_omid[(size_t)BN * MM * C2];    // [b][m][c]
__device__ __align__(1024) __nv_bfloat16 g_projB[(size_t)BN * MM * C2];   // [b][t][c']

// ---------------- helpers ----------------
__device__ __forceinline__ uint32_t smem_u32(const void* p) {
    uint32_t a;
    asm("{ .reg .u64 t; cvta.to.shared.u64 t, %1; cvt.u32.u64 %0, t; }" : "=r"(a) : "l"(p));
    return a;
}
__device__ __forceinline__ uint32_t bf16pack(float lo, float hi) {
    uint32_t r;
    asm("cvt.rn.bf16x2.f32 %0, %1, %2;" : "=r"(r) : "f"(hi), "f"(lo));
    return r;
}
#define CP16(dst, src) \
    asm volatile("cp.async.cg.shared.global [%0], [%1], 16;" :: "r"(dst), "l"(src) : "memory")
#define CPCOMMIT() asm volatile("cp.async.commit_group;" ::: "memory")
#define CPWAIT(n) asm volatile("cp.async.wait_group %0;" :: "n"(n) : "memory")

__device__ __forceinline__ void ldsm_x4(uint32_t* r, uint32_t addr) {
    asm volatile("ldmatrix.sync.aligned.m8n8.x4.shared.b16 {%0,%1,%2,%3}, [%4];"
        : "=r"(r[0]), "=r"(r[1]), "=r"(r[2]), "=r"(r[3]) : "r"(addr));
}
__device__ __forceinline__ void mma16816(float* c, const uint32_t* a, const uint32_t* b) {
    asm volatile("mma.sync.aligned.m16n8k16.row.col.f32.bf16.bf16.f32 "
        "{%0,%1,%2,%3}, {%4,%5,%6,%7}, {%8,%9}, {%0,%1,%2,%3};"
        : "+f"(c[0]), "+f"(c[1]), "+f"(c[2]), "+f"(c[3])
        : "r"(a[0]), "r"(a[1]), "r"(a[2]), "r"(a[3]), "r"(b[0]), "r"(b[1]));
}

#define STG 32768
#define GEMM_SMEM (3 * STG)

// ---------------- HMMA GEMM: 128x128 CTA tile, BK=64, 3-stage cp.async ----------------
// D[i][j] = sum_k A[m0+i][k] * B[n0+j][k]; A,B K-major bf16.
// EPI: 0 none (bf16)
//      1 +aux1[row] (bf16)
//      2 cov transform + exp + SYMMETRIC (grid.x=36 tile pairs, mirror write),
//        atomic row sums into aux2 (bf16 out)
//      3 +aux1[row]+aux2 residual (fp32 out)
//      4 +aux1[col], atomic row-sums into aux2 (bf16 out)
//      5 *(1/aux1[row]) (bf16 out)
template <int EPI>
__global__ __launch_bounds__(256, 2)
void mma_gemm(const __nv_bfloat16* __restrict__ A, int lda, size_t sA,
              const __nv_bfloat16* __restrict__ B, int ldb, size_t sB,
              void* __restrict__ Cv, int ldc, size_t sC, int K,
              const float* __restrict__ aux1, size_t sX1,
              const float* __restrict__ aux2, size_t sX2) {
    extern __shared__ __align__(128) char smem[];
    uint32_t sbase = smem_u32(smem);
    int t = threadIdx.x, l = t & 31, w = t >> 5;
    int bz = blockIdx.z;
    int m0, n0;
    if (EPI == 2) {
        int idx = blockIdx.x, by = 0;
        while (idx >= 8 - by) { idx -= 8 - by; by++; }
        m0 = by * 128;
        n0 = (by + idx) * 128;
    } else {
        m0 = blockIdx.y * 128;
        n0 = blockIdx.x * 128;
    }
    A += (size_t)bz * sA + (size_t)m0 * lda;
    B += (size_t)bz * sB + (size_t)n0 * ldb;
    int wm = w & 1, wn = w >> 1;

    float acc[4][4][4];
#pragma unroll
    for (int i = 0; i < 4; i++)
#pragma unroll
        for (int j = 0; j < 4; j++)
#pragma unroll
            for (int q = 0; q < 4; q++) acc[i][j][q] = 0.f;

    int pidx = t * 4;
    int prow = pidx >> 3, pch0 = pidx & 7;
    int la = (l & 7) + ((l >> 3) & 1) * 8;
    int akb = l >> 4;
    uint32_t aRow = (uint32_t)(wm * 64 + la) * 128;
    int bkb = (l >> 3) & 1;
    uint32_t bRow = 16384u + (uint32_t)(wn * 32 + ((l >> 4) << 3) + (l & 7)) * 128;
    int swz = l & 7;
    int pswz = prow & 7;

    int nk = K >> 6;
#pragma unroll
    for (int c = 0; c < 2; c++) {
        uint32_t so = (uint32_t)c * STG;
        int k0 = c * 64;
#pragma unroll
        for (int q = 0; q < 4; q++) {
            int ch = pch0 + q;
            uint32_t po = so + (uint32_t)prow * 128 + (uint32_t)((ch ^ pswz) << 4);
            CP16(po + sbase, A + (size_t)prow * lda + k0 + ch * 8);
            CP16(po + sbase + 16384, B + (size_t)prow * ldb + k0 + ch * 8);
        }
        CPCOMMIT();
    }

    for (int c = 0; c < nk; c++) {
        if (c + 1 < nk) { CPWAIT(1); } else { CPWAIT(0); }
        __syncthreads();
        if (c + 2 < nk) {
            int cs = c + 2;
            uint32_t so = (uint32_t)(cs % 3) * STG;
            int k0 = cs * 64;
#pragma unroll
            for (int q = 0; q < 4; q++) {
                int ch = pch0 + q;
                uint32_t po = so + (uint32_t)prow * 128 + (uint32_t)((ch ^ pswz) << 4);
                CP16(po + sbase, A + (size_t)prow * lda + k0 + ch * 8);
                CP16(po + sbase + 16384, B + (size_t)prow * ldb + k0 + ch * 8);
            }
            CPCOMMIT();
        }
        uint32_t so = sbase + (uint32_t)(c % 3) * STG;
#pragma unroll
        for (int ks = 0; ks < 4; ks++) {
            uint32_t af[4][4], bfr[2][4];
            uint32_t aoff = (uint32_t)(((ks * 2 + akb) ^ swz) << 4);
#pragma unroll
            for (int mt = 0; mt < 4; mt++)
                ldsm_x4(af[mt], so + aRow + (uint32_t)mt * 2048 + aoff);
            uint32_t boff = (uint32_t)(((ks * 2 + bkb) ^ swz) << 4);
#pragma unroll
            for (int np = 0; np < 2; np++)
                ldsm_x4(bfr[np], so + bRow + (uint32_t)np * 2048 + boff);
#pragma unroll
            for (int mt = 0; mt < 4; mt++) {
                mma16816(acc[mt][0], af[mt], &bfr[0][0]);
                mma16816(acc[mt][1], af[mt], &bfr[0][2]);
                mma16816(acc[mt][2], af[mt], &bfr[1][0]);
                mma16816(acc[mt][3], af[mt], &bfr[1][2]);
            }
        }
    }

    // ---------------- epilogue ----------------
    int qr = l >> 2, qc = (l & 3) * 2;
    const float* s1 = aux1 ? (aux1 + (size_t)bz * sX1) : nullptr;
    const float INV_M = 1.0f / 1024.0f;
    const float INV_M2 = INV_M * INV_M;

    if (EPI == 2) {
        __nv_bfloat16* C = (__nv_bfloat16*)Cv + (size_t)bz * sC;
        float* zout = (float*)aux2 + (size_t)bz * sX2;
        bool mirror = (n0 != m0);
        float cs0[4] = {0.f, 0.f, 0.f, 0.f}, cs1[4] = {0.f, 0.f, 0.f, 0.f};
#pragma unroll
        for (int mt = 0; mt < 4; mt++) {
            int r0 = m0 + wm * 64 + mt * 16 + qr;
            int r1 = r0 + 8;
            float sr0 = s1[r0], sr1 = s1[r1];
            float p0 = 0.f, p1 = 0.f;
#pragma unroll
            for (int nt = 0; nt < 4; nt++) {
                int cn = n0 + wn * 32 + nt * 8 + qc;
                float sc0 = s1[cn], sc1 = s1[cn + 1];
                float v0 = __expf((acc[mt][nt][0] * INV_M - sr0 * sc0 * INV_M2) * 0.0625f);
                float v1 = __expf((acc[mt][nt][1] * INV_M - sr0 * sc1 * INV_M2) * 0.0625f);
                float v2 = __expf((acc[mt][nt][2] * INV_M - sr1 * sc0 * INV_M2) * 0.0625f);
                float v3 = __expf((acc[mt][nt][3] * INV_M - sr1 * sc1 * INV_M2) * 0.0625f);
                acc[mt][nt][0] = v0; acc[mt][nt][1] = v1;
                acc[mt][nt][2] = v2; acc[mt][nt][3] = v3;
                p0 += v0 + v1; p1 += v2 + v3;
                cs0[nt] += v0 + v2; cs1[nt] += v1 + v3;
                *(uint32_t*)&C[(size_t)r0 * ldc + cn] = bf16pack(v0, v1);
                *(uint32_t*)&C[(size_t)r1 * ldc + cn] = bf16pack(v2, v3);
            }
            p0 += __shfl_xor_sync(0xffffffffu, p0, 1);
            p0 += __shfl_xor_sync(0xffffffffu, p0, 2);
            p1 += __shfl_xor_sync(0xffffffffu, p1, 1);
            p1 += __shfl_xor_sync(0xffffffffu, p1, 2);
            if ((l & 3) == 0) {
                atomicAdd(&zout[r0], p0);
                atomicAdd(&zout[r1], p1);
            }
        }
        if (mirror) {
            // column sums -> rows of mirrored tile
#pragma unroll
            for (int nt = 0; nt < 4; nt++) {
                float a = cs0[nt], b = cs1[nt];
                a += __shfl_xor_sync(0xffffffffu, a, 4);
                a += __shfl_xor_sync(0xffffffffu, a, 8);
                a += __shfl_xor_sync(0xffffffffu, a, 16);
                b += __shfl_xor_sync(0xffffffffu, b, 4);
                b += __shfl_xor_sync(0xffffffffu, b, 8);
                b += __shfl_xor_sync(0xffffffffu, b, 16);
                if (l < 4) {
                    int cn = n0 + wn * 32 + nt * 8 + (l & 3) * 2;
                    atomicAdd(&zout[cn], a);
                    atomicAdd(&zout[cn + 1], b);
                }
            }
            // staged transposed write (coalesced)
            __syncthreads();
            __nv_bfloat16* st = (__nv_bfloat16*)smem;    // [128][136] bf16
#pragma unroll
            for (int mt = 0; mt < 4; mt++) {
                int rl0 = wm * 64 + mt * 16 + qr;
                int rl1 = rl0 + 8;
#pragma unroll
                for (int nt = 0; nt < 4; nt++) {
                    int cl = wn * 32 + nt * 8 + qc;
                    st[cl * 136 + rl0] = __float2bfloat16(acc[mt][nt][0]);
                    st[(cl + 1) * 136 + rl0] = __float2bfloat16(acc[mt][nt][1]);
                    st[cl * 136 + rl1] = __float2bfloat16(acc[mt][nt][2]);
                    st[(cl + 1) * 136 + rl1] = __float2bfloat16(acc[mt][nt][3]);
                }
            }
            __syncthreads();
#pragma unroll
            for (int i = 0; i < 8; i++) {
                int idx = t + i * 256;            // 2048 uint4 chunks
                int row = idx >> 4, ch = idx & 15;
                uint4 val = *(const uint4*)(st + row * 136 + ch * 8);
                *(uint4*)&C[(size_t)(n0 + row) * ldc + m0 + ch * 8] = val;
            }
        }
    } else if (EPI != 3) {
        __nv_bfloat16* C = (__nv_bfloat16*)Cv + (size_t)bz * sC;
        float* zout = (EPI == 4) ? ((float*)aux2 + (size_t)bz * sX2) : nullptr;
#pragma unroll
        for (int mt = 0; mt < 4; mt++) {
            int r0 = m0 + wm * 64 + mt * 16 + qr;
            int r1 = r0 + 8;
            float add0 = 0.f, add1 = 0.f;
            if (EPI == 1) { add0 = s1[r0]; add1 = s1[r1]; }
            if (EPI == 5) { add0 = __frcp_rn(s1[r0]); add1 = __frcp_rn(s1[r1]); }
            float p0 = 0.f, p1 = 0.f;
#pragma unroll
            for (int nt = 0; nt < 4; nt++) {
                int cn = n0 + wn * 32 + nt * 8 + qc;
                float v0 = acc[mt][nt][0], v1 = acc[mt][nt][1];
                float v2 = acc[mt][nt][2], v3 = acc[mt][nt][3];
                if (EPI == 1) { v0 += add0; v1 += add0; v2 += add1; v3 += add1; }
                if (EPI == 5) { v0 *= add0; v1 *= add0; v2 *= add1; v3 *= add1; }
                if (EPI == 4) {
                    float sc0 = s1[cn], sc1 = s1[cn + 1];
                    v0 += sc0; v1 += sc1; v2 += sc0; v3 += sc1;
                    p0 += v0 + v1; p1 += v2 + v3;
                }
                *(uint32_t*)&C[(size_t)r0 * ldc + cn] = bf16pack(v0, v1);
                *(uint32_t*)&C[(size_t)r1 * ldc + cn] = bf16pack(v2, v3);
            }
            if (EPI == 4) {
                p0 += __shfl_xor_sync(0xffffffffu, p0, 1);
                p0 += __shfl_xor_sync(0xffffffffu, p0, 2);
                p1 += __shfl_xor_sync(0xffffffffu, p1, 1);
                p1 += __shfl_xor_sync(0xffffffffu, p1, 2);
                if ((l & 3) == 0) {
                    atomicAdd(&zout[r0], p0);
                    atomicAdd(&zout[r1], p1);
                }
            }
        }
    } else {
        float* C = (float*)Cv + (size_t)bz * sC;
        const float* xr = aux2 + (size_t)bz * sX2;
#pragma unroll
        for (int mt = 0; mt < 4; mt++) {
            int r0 = m0 + wm * 64 + mt * 16 + qr;
            int r1 = r0 + 8;
            float b0 = s1[r0], b1 = s1[r1];
#pragma unroll
            for (int nt = 0; nt < 4; nt++) {
                int cn = n0 + wn * 32 + nt * 8 + qc;
                float2 x0 = *(const float2*)&xr[(size_t)r0 * ldc + cn];
                float2 x1 = *(const float2*)&xr[(size_t)r1 * ldc + cn];
                float2 o0, o1;
                o0.x = acc[mt][nt][0] + b0 + x0.x;
                o0.y = acc[mt][nt][1] + b0 + x0.y;
                o1.x = acc[mt][nt][2] + b1 + x1.x;
                o1.y = acc[mt][nt][3] + b1 + x1.y;
                *(float2*)&C[(size_t)r0 * ldc + cn] = o0;
                *(float2*)&C[(size_t)r1 * ldc + cn] = o1;
            }
        }
    }
}

// ---------------- transposes: coalesced 128B writes ----------------
// f32 src [Rs][Cs] -> bf16 dst [Cs][Rs]; tile src 64r x 32c; block (32,8)
__global__ void transpose_f32(const float* __restrict__ src, __nv_bfloat16* __restrict__ dst,
                              int Rs, int Cs, size_t sS, size_t sD) {
    __shared__ float tile[32][65];
    int bz = blockIdx.z;
    src += (size_t)bz * sS;
    dst += (size_t)bz * sD;
    int c0 = blockIdx.x * 32, r0 = blockIdx.y * 64;
    int tx = threadIdx.x, ty = threadIdx.y;
#pragma unroll
    for (int i = 0; i < 8; i++) {
        int r = ty + 8 * i;
        tile[tx][r] = src[(size_t)(r0 + r) * Cs + c0 + tx];
    }
    __syncthreads();
    int t = ty * 32 + tx;
    int row = t >> 3, ch = t & 7;          // 32 rows x 8 chunks of 8 bf16
    float f[8];
#pragma unroll
    for (int q = 0; q < 8; q++) f[q] = tile[row][ch * 8 + q];
    uint4 o;
    o.x = bf16pack(f[0], f[1]); o.y = bf16pack(f[2], f[3]);
    o.z = bf16pack(f[4], f[5]); o.w = bf16pack(f[6], f[7]);
    *(uint4*)&dst[(size_t)(c0 + row) * Rs + r0 + ch * 8] = o;
}

// bf16 src [Rs][Cs] -> bf16 dst [Cs][Rs]; tile src 64r x 64c; block (32,8)
__global__ void transpose_bf16(const __nv_bfloat16* __restrict__ src, __nv_bfloat16* __restrict__ dst,
                               int Rs, int Cs, size_t sS, size_t sD) {
    __shared__ float tile[64][65];
    int bz = blockIdx.z;
    src += (size_t)bz * sS;
    dst += (size_t)bz * sD;
    int c0 = blockIdx.x * 64, r0 = blockIdx.y * 64;
    int tx = threadIdx.x, ty = threadIdx.y;
#pragma unroll
    for (int i = 0; i < 8; i++) {
        int r = ty + 8 * i;
        __nv_bfloat162 p = *(const __nv_bfloat162*)&src[(size_t)(r0 + r) * Cs + c0 + tx * 2];
        float2 f = __bfloat1622float2(p);
        tile[tx * 2][r] = f.x;
        tile[tx * 2 + 1][r] = f.y;
    }
    __syncthreads();
    int t = ty * 32 + tx;
#pragma unroll
    for (int i = 0; i < 2; i++) {
        int idx = t + i * 256;
        int row = idx >> 3, ch = idx & 7;   // 64 rows x 8 chunks
        float f[8];
#pragma unroll
        for (int q = 0; q < 8; q++) f[q] = tile[row][ch * 8 + q];
        uint4 o;
        o.x = bf16pack(f[0], f[1]); o.y = bf16pack(f[2], f[3]);
        o.z = bf16pack(f[4], f[5]); o.w = bf16pack(f[6], f[7]);
        *(uint4*)&dst[(size_t)(c0 + row) * Rs + r0 + ch * 8] = o;
    }
}

// ---------------- small kernels ----------------
__global__ void pack_weights(const float* __restrict__ Wk, const float* __restrict__ Wv,
                             const float* __restrict__ Wo) {
    int i = blockIdx.x * 256 + threadIdx.x;   // 0..131071
    g_wk[i] = __float2bfloat16(Wk[i]);
    g_wv[i] = __float2bfloat16(Wv[i]);
    g_wo[i] = __float2bfloat16(Wo[i]);
    if (i < BN * MM) { g_s[i] = 0.f; g_z[i] = 0.f; }
}

// ---------------- launch ----------------
extern "C" void kernel_launch(void* const* d_in, const int* in_sizes, int n_in,
                              void* d_out, int out_size) {
    const float* x = (const float*)d_in[0];
    const float* Wk = (const float*)d_in[1];
    const float* bk = (const float*)d_in[2];
    const float* Wv = (const float*)d_in[3];
    const float* bv = (const float*)d_in[4];
    const float* Wo = (const float*)d_in[5];
    const float* bo = (const float*)d_in[6];
    float* out = (float*)d_out;

    __nv_bfloat16 *xT, *wk, *wv, *wo, *kT, *v, *vT, *attn, *omid, *projB;
    float *s, *z;
    cudaGetSymbolAddress((void**)&xT, g_xT);
    cudaGetSymbolAddress((void**)&wk, g_wk);
    cudaGetSymbolAddress((void**)&wv, g_wv);
    cudaGetSymbolAddress((void**)&wo, g_wo);
    cudaGetSymbolAddress((void**)&kT, g_kT);
    cudaGetSymbolAddress((void**)&v, g_v);
    cudaGetSymbolAddress((void**)&vT, g_vT);
    cudaGetSymbolAddress((void**)&attn, g_attn);
    cudaGetSymbolAddress((void**)&omid, g_omid);
    cudaGetSymbolAddress((void**)&projB, g_projB);
    cudaGetSymbolAddress((void**)&s, g_s);
    cudaGetSymbolAddress((void**)&z, g_z);

    cudaFuncSetAttribute(mma_gemm<1>, cudaFuncAttributeMaxDynamicSharedMemorySize, GEMM_SMEM);
    cudaFuncSetAttribute(mma_gemm<2>, cudaFuncAttributeMaxDynamicSharedMemorySize, GEMM_SMEM);
    cudaFuncSetAttribute(mma_gemm<3>, cudaFuncAttributeMaxDynamicSharedMemorySize, GEMM_SMEM);
    cudaFuncSetAttribute(mma_gemm<4>, cudaFuncAttributeMaxDynamicSharedMemorySize, GEMM_SMEM);
    cudaFuncSetAttribute(mma_gemm<5>, cudaFuncAttributeMaxDynamicSharedMemorySize, GEMM_SMEM);

    dim3 t328(32, 8);

    // 1. weights -> bf16; zero s/z accumulators
    pack_weights<<<512, 256>>>(Wk, Wv, Wo);
    // 2. xT[b] = x[b]^T  [1024][512] bf16   (src f32 [512][1024])
    transpose_f32<<<dim3(32, 8, 32), t328>>>(x, xT, 512, 1024, 524288, 524288);
    // 3a. kT[b][m][c] = xT @ Wk^T + bk[col]; s[m] accumulated via atomics
    mma_gemm<4><<<dim3(2, 8, 32), 256, GEMM_SMEM>>>(xT, 512, 524288, wk, 512, 0,
                                                    kT, 256, 262144, 512, bk, 0, s, 1024);
    // 3b. v[b][c][m] = Wv @ x + bv[row]
    mma_gemm<1><<<dim3(8, 2, 32), 256, GEMM_SMEM>>>(wv, 512, 0, xT, 512, 524288,
                                                    v, 1024, 262144, 512, bv, 0, nullptr, 0);
    // 4. vT[b] = (v viewed [1024][256])^T -> [256][1024]
    transpose_bf16<<<dim3(4, 16, 32), t328>>>(v, vT, 1024, 256, 262144, 262144);
    // 5. attn = exp(cov * c2^-0.5), symmetric: 36 tile pairs; z row sums via atomics
    mma_gemm<2><<<dim3(36, 1, 32), 256, GEMM_SMEM>>>(kT, 256, 262144, kT, 256, 262144,
                                                     attn, 1024, 1048576, 256, s, 1024, z, 1024);
    // 6. omid[b][m][c] = (attn @ V) / z[m]
    mma_gemm<5><<<dim3(2, 8, 32), 256, GEMM_SMEM>>>(attn, 1024, 1048576, vT, 1024, 262144,
                                                    omid, 256, 262144, 1024, z, 1024, nullptr, 0);
    // 7. projB[b] = (omid viewed [256][1024])^T -> [1024][256]
    transpose_bf16<<<dim3(16, 4, 32), t328>>>(omid, projB, 256, 1024, 262144, 262144);
    // 8. out = Wo @ Y + bo + x   (fp32 out)
    mma_gemm<3><<<dim3(8, 4, 32), 256, GEMM_SMEM>>>(wo, 256, 0, projB, 256, 262144,
                                                    out, 1024, 524288, 256, bo, 0, x, 524288);
}